// round 1
// baseline (speedup 1.0000x reference)
#include <cuda_runtime.h>
#include <cuda_bf16.h>

// PositionalEncoding: out[b,s,e] = x[b,s,e] + (e even ? sin : cos)(s / 10000^(2e/E))
// x: [B=8, S=4096, E=1024] fp32.
//
// Strategy: pe depends only on (s,e). One thread owns a float4 along e for a
// fixed s, computes the 4 pe values once in registers (2 sin + 2 cos, fast
// polynomial path since |angle| <= 4095 << 1e5), then streams all 8 batches
// with independent float4 loads/stores (MLP=8). Pure HBM-bound: 256 MB total.

static constexpr int S = 4096;
static constexpr int E = 1024;
static constexpr int B = 8;

__global__ __launch_bounds__(256, 8)
void pe_add_kernel(const float* __restrict__ x, float* __restrict__ out) {
    const int s  = blockIdx.x;          // 0..4095
    const int t  = threadIdx.x;         // 0..255
    const int e0 = t * 4;               // float4 start, always even

    const float pos = (float)s;
    // 10000^(-2j/E) = exp2f(j * (-2*log2(10000)/E))
    const float c = -2.0f * 13.287712379549449f / (float)E;

    float pe0, pe1, pe2, pe3;
    {
        // j = e0+0 (even -> sin), e0+1 (odd -> cos), e0+2 (sin), e0+3 (cos)
        float a0 = pos * exp2f(c * (float)(e0 + 0));
        float a1 = pos * exp2f(c * (float)(e0 + 1));
        float a2 = pos * exp2f(c * (float)(e0 + 2));
        float a3 = pos * exp2f(c * (float)(e0 + 3));
        pe0 = sinf(a0);
        pe1 = cosf(a1);
        pe2 = sinf(a2);
        pe3 = cosf(a3);
    }

    const size_t SE   = (size_t)S * (size_t)E;
    const size_t base = (size_t)s * (size_t)E + (size_t)e0;

#pragma unroll
    for (int b = 0; b < B; b++) {
        const size_t off = (size_t)b * SE + base;
        float4 v = *reinterpret_cast<const float4*>(x + off);
        v.x += pe0;
        v.y += pe1;
        v.z += pe2;
        v.w += pe3;
        *reinterpret_cast<float4*>(out + off) = v;
    }
}

extern "C" void kernel_launch(void* const* d_in, const int* in_sizes, int n_in,
                              void* d_out, int out_size) {
    const float* x = (const float*)d_in[0];
    float* out     = (float*)d_out;
    (void)in_sizes; (void)n_in; (void)out_size;

    dim3 grid(S);        // one block per sequence position
    dim3 block(E / 4);   // 256 threads, one float4 each
    pe_add_kernel<<<grid, block>>>(x, out);
}

// round 9
// speedup vs baseline: 1.0365x; 1.0365x over previous
#include <cuda_runtime.h>
#include <cuda_bf16.h>

// PositionalEncoding: out[b,s,e] = x[b,s,e] + (e even ? sin : cos)(s / 10000^(2e/E))
// x: [B=8, S=4096, E=1024] fp32. Pure HBM stream: 128 MB in + 128 MB out.
//
// R1 analysis: DRAM=74.2% with regs=32 -> MLP-starved (loop was pipelined as
// load/add/store pairs). Fix: allow 64 regs and batch ALL 8 float4 loads
// before any store (MLP_p1=8), with streaming cache hints (.cs) since every
// byte is touched exactly once.

static constexpr int S = 4096;
static constexpr int E = 1024;
static constexpr int B = 8;

__global__ __launch_bounds__(256, 4)
void pe_add_kernel(const float* __restrict__ x, float* __restrict__ out) {
    const int s  = blockIdx.x;          // 0..4095
    const int t  = threadIdx.x;         // 0..255
    const int e0 = t * 4;               // float4 start, always even

    const size_t SE   = (size_t)S * (size_t)E;
    const size_t base = (size_t)s * (size_t)E + (size_t)e0;

    // ---- Phase 1: batch all 8 independent 128-bit loads (MLP=8) ----
    float4 v[B];
#pragma unroll
    for (int b = 0; b < B; b++) {
        v[b] = __ldcs(reinterpret_cast<const float4*>(x + b * SE + base));
    }

    // ---- Phase 2: compute pe for this (s, e0..e0+3) once (hidden under loads) ----
    const float pos = (float)s;
    // 10000^(-2j/E) = exp2f(j * (-2*log2(10000)/E))
    const float c = -2.0f * 13.287712379549449f / (float)E;

    const float a0 = pos * exp2f(c * (float)(e0 + 0));
    const float a1 = pos * exp2f(c * (float)(e0 + 1));
    const float a2 = pos * exp2f(c * (float)(e0 + 2));
    const float a3 = pos * exp2f(c * (float)(e0 + 3));
    const float pe0 = sinf(a0);  // even index -> sin
    const float pe1 = cosf(a1);  // odd  index -> cos
    const float pe2 = sinf(a2);
    const float pe3 = cosf(a3);

    // ---- Phase 3: add + streaming stores ----
#pragma unroll
    for (int b = 0; b < B; b++) {
        float4 r = v[b];
        r.x += pe0;
        r.y += pe1;
        r.z += pe2;
        r.w += pe3;
        __stcs(reinterpret_cast<float4*>(out + b * SE + base), r);
    }
}

extern "C" void kernel_launch(void* const* d_in, const int* in_sizes, int n_in,
                              void* d_out, int out_size) {
    const float* x = (const float*)d_in[0];
    float* out     = (float*)d_out;
    (void)in_sizes; (void)n_in; (void)out_size;

    dim3 grid(S);        // one block per sequence position
    dim3 block(E / 4);   // 256 threads, one float4 each
    pe_add_kernel<<<grid, block>>>(x, out);
}